// round 7
// baseline (speedup 1.0000x reference)
#include <cuda_runtime.h>
#include <cuda_fp16.h>
#include <cstdint>
#include <cstddef>

#define D_   2048
#define NC_  2
#define DS_  16
#define BL_  1024           // B*L = 2*512
#define N1_  4096           // NC*D

// ---------------- scratch (static device globals; no allocation) -----------
__device__ __half g_Wh1[(size_t)N1_ * D_];   // fp16 W_in   (16 MB)
__device__ __half g_Wh2[(size_t)D_ * N1_];   // fp16 W_out  (16 MB)
__device__ __half g_xh [(size_t)BL_ * D_];   // fp16 x      (2 MB)
__device__ __half g_yh [(size_t)BL_ * N1_];  // fp16 y = xi*gate (8 MB)
__device__ float  g_o  [(size_t)BL_ * D_];   // out pre-norm (8 MB)
__device__ float  g_gate[N1_];

// ---------------- helpers ---------------------------------------------------
__device__ __forceinline__ void cpa16(const void* s, const void* g) {
    unsigned sa = (unsigned)__cvta_generic_to_shared(s);
    asm volatile("cp.async.cg.shared.global [%0], [%1], 16;\n" :: "r"(sa), "l"(g));
}
__device__ __forceinline__ void ldsm4(unsigned& r0, unsigned& r1,
                                      unsigned& r2, unsigned& r3, uint32_t a) {
    asm volatile("ldmatrix.sync.aligned.m8n8.x4.shared.b16 {%0,%1,%2,%3}, [%4];"
                 : "=r"(r0), "=r"(r1), "=r"(r2), "=r"(r3) : "r"(a));
}
__device__ __forceinline__ void stcs(float4* p, float4 v) {
    asm volatile("st.global.cs.v4.f32 [%0], {%1,%2,%3,%4};"
                 :: "l"(p), "f"(v.x), "f"(v.y), "f"(v.z), "f"(v.w) : "memory");
}

// ---------------- fp32 -> fp16 convert (all 3 tensors, one launch) ----------
__global__ void to_half_all(const float4* __restrict__ a, __half2* __restrict__ da, int na,
                            const float4* __restrict__ b, __half2* __restrict__ db, int nb,
                            const float4* __restrict__ c, __half2* __restrict__ dc, int nc) {
    int i = blockIdx.x * blockDim.x + threadIdx.x;
    const float4* s; __half2* d; int idx;
    if (i < na)           { s = a; d = da; idx = i; }
    else if (i < na + nb) { s = b; d = db; idx = i - na; }
    else if (i < na + nb + nc) { s = c; d = dc; idx = i - na - nb; }
    else return;
    float4 v = s[idx];
    d[2 * idx]     = __floats2half2_rn(v.x, v.y);
    d[2 * idx + 1] = __floats2half2_rn(v.z, v.w);
}

// ---------------- gate: g[n] = sum_ds(Cr*Br - Ci*Bi), 4 lanes per n ---------
__global__ void compute_gate(const float4* __restrict__ Br, const float4* __restrict__ Bi,
                             const float4* __restrict__ Cr, const float4* __restrict__ Ci) {
    int t = blockIdx.x * blockDim.x + threadIdx.x;   // 0 .. 4*N1_-1
    int n = t >> 2, j = t & 3;
    if (n >= N1_) return;
    float4 cr = Cr[n * 4 + j], br = Br[n * 4 + j];
    float4 ci = Ci[n * 4 + j], bi = Bi[n * 4 + j];
    float s = 0.f;
    s = fmaf(cr.x, br.x, s); s = fmaf(-ci.x, bi.x, s);
    s = fmaf(cr.y, br.y, s); s = fmaf(-ci.y, bi.y, s);
    s = fmaf(cr.z, br.z, s); s = fmaf(-ci.z, bi.z, s);
    s = fmaf(cr.w, br.w, s); s = fmaf(-ci.w, bi.w, s);
    s += __shfl_down_sync(0xFFFFFFFFu, s, 2);
    s += __shfl_down_sync(0xFFFFFFFFu, s, 1);
    if (j == 0) g_gate[n] = s;
}

// ---------------- state emission helper (streaming stores) ------------------
__device__ __forceinline__ void emit_state(float* __restrict__ nr, float* __restrict__ ni,
                                           const float4* __restrict__ brp,
                                           const float4* __restrict__ bip,
                                           int row, int col, float v) {
    size_t off = ((size_t)row * N1_ + col) * 4;          // float4 units
    float4* pr = reinterpret_cast<float4*>(nr) + off;
    float4* pi = reinterpret_cast<float4*>(ni) + off;
    #pragma unroll
    for (int jj = 0; jj < 4; jj++) {
        float4 b = __ldg(&brp[(size_t)col * 4 + jj]);
        stcs(&pr[jj], make_float4(b.x * v, b.y * v, b.z * v, b.w * v));
    }
    #pragma unroll
    for (int jj = 0; jj < 4; jj++) {
        float4 b = __ldg(&bip[(size_t)col * 4 + jj]);
        stcs(&pi[jj], make_float4(b.x * v, b.y * v, b.z * v, b.w * v));
    }
}

// ---------------- TN GEMM: C[M,N] = A[M,K] * B[N,K]^T (fp16 mma + ldmatrix) -
// BM x 128 CTA tile, BK=32 halves, 5-stage cp.async pipeline, 256 threads.
template<int BM, bool FUSED>
__global__ __launch_bounds__(256, 2) void gemm_tn(
    const __half* __restrict__ A, const __half* __restrict__ B,
    float* __restrict__ Cf, __half* __restrict__ Ch, int ldc, int K,
    const float* __restrict__ Brs, const float* __restrict__ Bis,
    float* __restrict__ nr, float* __restrict__ ni, int write_state)
{
    constexpr int S   = 5;                    // pipeline stages
    constexpr int RS  = 40;                   // halves per smem row (32 + 8 pad)
    constexpr int WR  = (BM == 128) ? 4 : 2;  // warps along m
    constexpr int WNS = (BM == 128) ? 64 : 32;// warp n-extent
    constexpr int JN  = WNS / 8;
    constexpr int JP  = JN / 2;               // ldmatrix B pairs
    constexpr int AST = BM  * RS;             // halves per A stage
    constexpr int BST = 128 * RS;

    extern __shared__ __half sm[];
    __half* As = sm;
    __half* Bs = sm + S * AST;

    const int tid  = threadIdx.x;
    const int lane = tid & 31;
    const int wid  = tid >> 5;
    const int wm   = (wid % WR) * 32;
    const int wn   = (wid / WR) * WNS;
    const int gid  = lane >> 2;
    const int q    = lane & 3;
    const int row0 = blockIdx.y * BM;
    const int col0 = blockIdx.x * 128;

    const int lr = tid >> 2;                  // loader row
    const int ls = (tid & 3) * 8;             // loader half-offset (16B = 8 halves)

    // ldmatrix per-lane address offsets (bytes)
    const int lr8 = lane & 7;
    const int lg  = lane >> 3;                // 0..3
    const uint32_t sm_u = (uint32_t)__cvta_generic_to_shared(sm);
    const uint32_t A_u  = sm_u;
    const uint32_t B_u  = sm_u + S * AST * 2;
    const uint32_t a_off = (uint32_t)(((wm + (lg & 1) * 8 + lr8) * RS + (lg >> 1) * 8) * 2);
    const uint32_t b_off = (uint32_t)(((wn + (lg >> 1) * 8 + lr8) * RS + (lg & 1) * 8) * 2);

    float cr[2][JN][4];
    #pragma unroll
    for (int i = 0; i < 2; i++)
        #pragma unroll
        for (int j = 0; j < JN; j++)
            #pragma unroll
            for (int t = 0; t < 4; t++) cr[i][j][t] = 0.f;

    auto issue = [&](int st, int k0) {
        #pragma unroll
        for (int i = 0; i < BM / 64; i++) {
            int r = lr + i * 64;
            cpa16(&As[st * AST + r * RS + ls], A + (size_t)(row0 + r) * K + k0 + ls);
        }
        #pragma unroll
        for (int i = 0; i < 2; i++) {
            int r = lr + i * 64;
            cpa16(&Bs[st * BST + r * RS + ls], B + (size_t)(col0 + r) * K + k0 + ls);
        }
        asm volatile("cp.async.commit_group;\n");
    };

    auto compute = [&](int st) {
        const uint32_t ab = A_u + st * (AST * 2) + a_off;
        const uint32_t bb = B_u + st * (BST * 2) + b_off;
        unsigned a[2][2][4], bp[2][JP][4];
        // load ALL fragments for both k-halves first (overlap ldsm latency
        // of ks=1 with the ks=0 MMA stream)
        #pragma unroll
        for (int ks = 0; ks < 2; ks++) {
            const uint32_t kbb = ks * 32;         // 16 halves = 32 bytes
            #pragma unroll
            for (int i = 0; i < 2; i++)
                ldsm4(a[ks][i][0], a[ks][i][1], a[ks][i][2], a[ks][i][3],
                      ab + i * (16 * RS * 2) + kbb);
            #pragma unroll
            for (int jp = 0; jp < JP; jp++)
                ldsm4(bp[ks][jp][0], bp[ks][jp][1], bp[ks][jp][2], bp[ks][jp][3],
                      bb + jp * (16 * RS * 2) + kbb);
        }
        #pragma unroll
        for (int ks = 0; ks < 2; ks++)
            #pragma unroll
            for (int i = 0; i < 2; i++)
                #pragma unroll
                for (int j = 0; j < JN; j++) {
                    const unsigned b0 = bp[ks][j >> 1][(j & 1) * 2];
                    const unsigned b1 = bp[ks][j >> 1][(j & 1) * 2 + 1];
                    asm volatile(
                        "mma.sync.aligned.m16n8k16.row.col.f32.f16.f16.f32 "
                        "{%0,%1,%2,%3}, {%4,%5,%6,%7}, {%8,%9}, {%0,%1,%2,%3};\n"
                        : "+f"(cr[i][j][0]), "+f"(cr[i][j][1]),
                          "+f"(cr[i][j][2]), "+f"(cr[i][j][3])
                        : "r"(a[ks][i][0]), "r"(a[ks][i][1]),
                          "r"(a[ks][i][2]), "r"(a[ks][i][3]),
                          "r"(b0), "r"(b1));
                }
    };

    const int nt = K / 32;
    #pragma unroll
    for (int s = 0; s < S - 1; s++) issue(s, s * 32);
    asm volatile("cp.async.wait_group %0;\n" :: "n"(S - 2));
    __syncthreads();

    for (int kt = 0; kt < nt; kt++) {
        int nk = kt + S - 1;
        if (nk < nt) issue(nk % S, nk * 32);
        else asm volatile("cp.async.commit_group;\n");
        compute(kt % S);
        asm volatile("cp.async.wait_group %0;\n" :: "n"(S - 2));
        __syncthreads();
    }

    // ---------------- epilogue ----------------
    if (!FUSED) {
        #pragma unroll
        for (int i = 0; i < 2; i++)
            #pragma unroll
            for (int j = 0; j < JN; j++) {
                int r  = row0 + wm + i * 16 + gid;
                int cn = col0 + wn + j * 8 + q * 2;
                *reinterpret_cast<float2*>(Cf + (size_t)r * ldc + cn) =
                    make_float2(cr[i][j][0], cr[i][j][1]);
                *reinterpret_cast<float2*>(Cf + (size_t)(r + 8) * ldc + cn) =
                    make_float2(cr[i][j][2], cr[i][j][3]);
            }
    } else {
        const float4* brp = reinterpret_cast<const float4*>(Brs);
        const float4* bip = reinterpret_cast<const float4*>(Bis);
        #pragma unroll
        for (int i = 0; i < 2; i++)
            #pragma unroll
            for (int j = 0; j < JN; j++) {
                int r  = row0 + wm + i * 16 + gid;
                int cn = col0 + wn + j * 8 + q * 2;
                float g0 = g_gate[cn], g1 = g_gate[cn + 1];
                *reinterpret_cast<__half2*>(Ch + (size_t)r * ldc + cn) =
                    __floats2half2_rn(cr[i][j][0] * g0, cr[i][j][1] * g1);
                *reinterpret_cast<__half2*>(Ch + (size_t)(r + 8) * ldc + cn) =
                    __floats2half2_rn(cr[i][j][2] * g0, cr[i][j][3] * g1);
                if (write_state) {
                    emit_state(nr, ni, brp, bip, r,     cn,     cr[i][j][0]);
                    emit_state(nr, ni, brp, bip, r,     cn + 1, cr[i][j][1]);
                    emit_state(nr, ni, brp, bip, r + 8, cn,     cr[i][j][2]);
                    emit_state(nr, ni, brp, bip, r + 8, cn + 1, cr[i][j][3]);
                }
            }
    }
}

// ---------------- rmsnorm + residual ----------------------------------------
__global__ __launch_bounds__(256) void rms_kernel(const float* __restrict__ x,
                                                  const float* __restrict__ w,
                                                  float* __restrict__ out)
{
    const int row = blockIdx.x;
    const float* o = g_o + (size_t)row * D_;
    float s = 0.f;
    for (int d = threadIdx.x; d < D_; d += 256) {
        float v = o[d];
        s = fmaf(v, v, s);
    }
    __shared__ float red[8];
    #pragma unroll
    for (int off = 16; off; off >>= 1) s += __shfl_xor_sync(0xFFFFFFFFu, s, off);
    if ((threadIdx.x & 31) == 0) red[threadIdx.x >> 5] = s;
    __syncthreads();
    if (threadIdx.x < 8) {
        float t = red[threadIdx.x];
        #pragma unroll
        for (int off = 4; off; off >>= 1) t += __shfl_xor_sync(0xFFu, t, off);
        if (threadIdx.x == 0) red[0] = t;
    }
    __syncthreads();
    const float scale = rsqrtf(red[0] * (1.0f / D_) + 1.1920928955078125e-7f);
    for (int d = threadIdx.x; d < D_; d += 256) {
        out[(size_t)row * D_ + d] =
            x[(size_t)row * D_ + d] + o[d] * scale * w[d];
    }
}

// ---------------- launch -----------------------------------------------------
extern "C" void kernel_launch(void* const* d_in, const int* in_sizes, int n_in,
                              void* d_out, int out_size)
{
    const float* x     = (const float*)d_in[0];
    const float* W_in  = (const float*)d_in[1];
    const float* W_out = (const float*)d_in[2];
    // d_in[3] = A_theta: dead (initial state is zero)
    const float* Br    = (const float*)d_in[4];
    const float* Bi    = (const float*)d_in[5];
    const float* Cr    = (const float*)d_in[6];
    const float* Ci    = (const float*)d_in[7];
    const float* nw    = (const float*)d_in[8];

    float* out0 = (float*)d_out;
    const long long FULL =
        (long long)BL_ * D_ + 2LL * BL_ * N1_ * DS_;   // 136,314,880
    const int write_state = ((long long)out_size >= FULL) ? 1 : 0;
    float* nr = out0 + (size_t)BL_ * D_;
    float* ni = nr + (size_t)BL_ * N1_ * DS_;

    void *w1_p = nullptr, *w2_p = nullptr, *xh_p = nullptr, *yh_p = nullptr, *o_p = nullptr;
    cudaGetSymbolAddress(&w1_p, g_Wh1);
    cudaGetSymbolAddress(&w2_p, g_Wh2);
    cudaGetSymbolAddress(&xh_p, g_xh);
    cudaGetSymbolAddress(&yh_p, g_yh);
    cudaGetSymbolAddress(&o_p,  g_o);

    const int SM1 = 5 * (128 + 128) * 40 * 2;   // 102,400 B
    const int SM2 = 5 * ( 64 + 128) * 40 * 2;   //  76,800 B
    cudaFuncSetAttribute(gemm_tn<128, true >, cudaFuncAttributeMaxDynamicSharedMemorySize, SM1);
    cudaFuncSetAttribute(gemm_tn< 64, false>, cudaFuncAttributeMaxDynamicSharedMemorySize, SM2);

    // convert inputs to fp16 (single launch)
    const int na = N1_ * D_ / 4, nb = D_ * N1_ / 4, nc = BL_ * D_ / 4;
    to_half_all<<<(na + nb + nc + 255) / 256, 256>>>(
        (const float4*)W_in,  (__half2*)w1_p, na,
        (const float4*)W_out, (__half2*)w2_p, nb,
        (const float4*)x,     (__half2*)xh_p, nc);

    compute_gate<<<(4 * N1_) / 256, 256>>>((const float4*)Br, (const float4*)Bi,
                                           (const float4*)Cr, (const float4*)Ci);

    // GEMM1 (fused): xi = x @ W_in^T -> y(half) / nr / ni.  M=1024,N=4096,K=2048
    gemm_tn<128, true><<<dim3(N1_ / 128, BL_ / 128), 256, SM1>>>(
        (const __half*)xh_p, (const __half*)w1_p, nullptr, (__half*)yh_p, N1_, D_,
        Br, Bi, nr, ni, write_state);

    // GEMM2: out = y @ W_out^T.  M=1024,N=2048,K=4096  (64-row tiles -> 256 CTAs)
    gemm_tn<64, false><<<dim3(D_ / 128, BL_ / 64), 256, SM2>>>(
        (const __half*)yh_p, (const __half*)w2_p, (float*)o_p, nullptr, D_, N1_,
        nullptr, nullptr, nullptr, nullptr, 0);

    // out0 = x + rmsnorm(out) * norm_w
    rms_kernel<<<BL_, 256>>>(x, nw, out0);
}

// round 8
// speedup vs baseline: 1.0581x; 1.0581x over previous
#include <cuda_runtime.h>
#include <cuda_fp16.h>
#include <cstdint>
#include <cstddef>

#define D_   2048
#define NC_  2
#define DS_  16
#define BL_  1024           // B*L = 2*512
#define N1_  4096           // NC*D

// ---------------- scratch (static device globals; no allocation) -----------
__device__ __half g_Wh1[(size_t)N1_ * D_];   // fp16 W_in   (16 MB)
__device__ __half g_Wh2[(size_t)D_ * N1_];   // fp16 W_out  (16 MB)
__device__ __half g_xh [(size_t)BL_ * D_];   // fp16 x      (2 MB)
__device__ __half g_yh [(size_t)BL_ * N1_];  // fp16 y = xi*gate (8 MB)
__device__ float  g_o  [(size_t)BL_ * D_];   // out pre-norm (8 MB)
__device__ float  g_gate[N1_];

// ---------------- helpers ---------------------------------------------------
__device__ __forceinline__ void cpa16(const void* s, const void* g) {
    unsigned sa = (unsigned)__cvta_generic_to_shared(s);
    asm volatile("cp.async.cg.shared.global [%0], [%1], 16;\n" :: "r"(sa), "l"(g));
}
__device__ __forceinline__ void ldsm4(unsigned& r0, unsigned& r1,
                                      unsigned& r2, unsigned& r3, uint32_t a) {
    asm volatile("ldmatrix.sync.aligned.m8n8.x4.shared.b16 {%0,%1,%2,%3}, [%4];"
                 : "=r"(r0), "=r"(r1), "=r"(r2), "=r"(r3) : "r"(a));
}
__device__ __forceinline__ void stcs(float4* p, float4 v) {
    asm volatile("st.global.cs.v4.f32 [%0], {%1,%2,%3,%4};"
                 :: "l"(p), "f"(v.x), "f"(v.y), "f"(v.z), "f"(v.w) : "memory");
}

// ---------------- fp32 -> fp16 convert (all 3 tensors, one launch) ----------
__global__ void to_half_all(const float4* __restrict__ a, __half2* __restrict__ da, int na,
                            const float4* __restrict__ b, __half2* __restrict__ db, int nb,
                            const float4* __restrict__ c, __half2* __restrict__ dc, int nc) {
    int i = blockIdx.x * blockDim.x + threadIdx.x;
    const float4* s; __half2* d; int idx;
    if (i < na)           { s = a; d = da; idx = i; }
    else if (i < na + nb) { s = b; d = db; idx = i - na; }
    else if (i < na + nb + nc) { s = c; d = dc; idx = i - na - nb; }
    else return;
    float4 v = s[idx];
    d[2 * idx]     = __floats2half2_rn(v.x, v.y);
    d[2 * idx + 1] = __floats2half2_rn(v.z, v.w);
}

// ---------------- gate: g[n] = sum_ds(Cr*Br - Ci*Bi), 4 lanes per n ---------
__global__ void compute_gate(const float4* __restrict__ Br, const float4* __restrict__ Bi,
                             const float4* __restrict__ Cr, const float4* __restrict__ Ci) {
    int t = blockIdx.x * blockDim.x + threadIdx.x;   // 0 .. 4*N1_-1
    int n = t >> 2, j = t & 3;
    if (n >= N1_) return;
    float4 cr = Cr[n * 4 + j], br = Br[n * 4 + j];
    float4 ci = Ci[n * 4 + j], bi = Bi[n * 4 + j];
    float s = 0.f;
    s = fmaf(cr.x, br.x, s); s = fmaf(-ci.x, bi.x, s);
    s = fmaf(cr.y, br.y, s); s = fmaf(-ci.y, bi.y, s);
    s = fmaf(cr.z, br.z, s); s = fmaf(-ci.z, bi.z, s);
    s = fmaf(cr.w, br.w, s); s = fmaf(-ci.w, bi.w, s);
    s += __shfl_down_sync(0xFFFFFFFFu, s, 2);
    s += __shfl_down_sync(0xFFFFFFFFu, s, 1);
    if (j == 0) g_gate[n] = s;
}

// ---------------- state emission helper (streaming stores) ------------------
__device__ __forceinline__ void emit_state(float* __restrict__ nr, float* __restrict__ ni,
                                           const float4* __restrict__ brp,
                                           const float4* __restrict__ bip,
                                           int row, int col, float v) {
    size_t off = ((size_t)row * N1_ + col) * 4;          // float4 units
    float4* pr = reinterpret_cast<float4*>(nr) + off;
    float4* pi = reinterpret_cast<float4*>(ni) + off;
    #pragma unroll
    for (int jj = 0; jj < 4; jj++) {
        float4 b = __ldg(&brp[(size_t)col * 4 + jj]);
        stcs(&pr[jj], make_float4(b.x * v, b.y * v, b.z * v, b.w * v));
    }
    #pragma unroll
    for (int jj = 0; jj < 4; jj++) {
        float4 b = __ldg(&bip[(size_t)col * 4 + jj]);
        stcs(&pi[jj], make_float4(b.x * v, b.y * v, b.z * v, b.w * v));
    }
}

// ---------------- TN GEMM: C[M,N] = A[M,K] * B[N,K]^T (fp16 mma + ldmatrix) -
// 64 x 128 CTA tile, BK=64 halves, 4-stage cp.async pipeline, 256 threads.
template<bool FUSED>
__global__ __launch_bounds__(256, 2) void gemm_tn(
    const __half* __restrict__ A, const __half* __restrict__ B,
    float* __restrict__ Cf, __half* __restrict__ Ch, int ldc, int K,
    const float* __restrict__ Brs, const float* __restrict__ Bis,
    float* __restrict__ nr, float* __restrict__ ni, int write_state)
{
    constexpr int S   = 4;                    // pipeline stages
    constexpr int BM  = 64;
    constexpr int RS  = 72;                   // halves per smem row (64 + 8 pad)
    constexpr int WR  = 2;                    // warps along m
    constexpr int WNS = 32;                   // warp n-extent
    constexpr int JN  = WNS / 8;              // 4
    constexpr int JP  = JN / 2;               // 2 ldmatrix B pairs
    constexpr int AST = BM  * RS;             // halves per A stage
    constexpr int BST = 128 * RS;

    extern __shared__ __half sm[];
    __half* As = sm;
    __half* Bs = sm + S * AST;

    const int tid  = threadIdx.x;
    const int lane = tid & 31;
    const int wid  = tid >> 5;
    const int wm   = (wid % WR) * 32;
    const int wn   = (wid / WR) * WNS;
    const int gid  = lane >> 2;
    const int q    = lane & 3;
    const int row0 = blockIdx.y * BM;
    const int col0 = blockIdx.x * 128;

    const int lr = tid >> 3;                  // loader row (0..31)
    const int ls = (tid & 7) * 8;             // loader half-offset (16B = 8 halves)

    // ldmatrix per-lane address offsets (bytes)
    const int lr8 = lane & 7;
    const int lg  = lane >> 3;                // 0..3
    const uint32_t sm_u = (uint32_t)__cvta_generic_to_shared(sm);
    const uint32_t A_u  = sm_u;
    const uint32_t B_u  = sm_u + S * AST * 2;
    const uint32_t a_off = (uint32_t)(((wm + (lg & 1) * 8 + lr8) * RS + (lg >> 1) * 8) * 2);
    const uint32_t b_off = (uint32_t)(((wn + (lg >> 1) * 8 + lr8) * RS + (lg & 1) * 8) * 2);

    float cr[2][JN][4];
    #pragma unroll
    for (int i = 0; i < 2; i++)
        #pragma unroll
        for (int j = 0; j < JN; j++)
            #pragma unroll
            for (int t = 0; t < 4; t++) cr[i][j][t] = 0.f;

    auto issue = [&](int st, int k0) {
        #pragma unroll
        for (int i = 0; i < BM / 32; i++) {            // 2 A-row groups
            int r = lr + i * 32;
            cpa16(&As[st * AST + r * RS + ls], A + (size_t)(row0 + r) * K + k0 + ls);
        }
        #pragma unroll
        for (int i = 0; i < 4; i++) {                  // 4 B-row groups
            int r = lr + i * 32;
            cpa16(&Bs[st * BST + r * RS + ls], B + (size_t)(col0 + r) * K + k0 + ls);
        }
        asm volatile("cp.async.commit_group;\n");
    };

    auto compute = [&](int st) {
        const uint32_t ab = A_u + st * (AST * 2) + a_off;
        const uint32_t bb = B_u + st * (BST * 2) + b_off;
        #pragma unroll
        for (int ks = 0; ks < 4; ks++) {               // 4 k-halves of 16
            const uint32_t kbb = ks * 32;              // 16 halves = 32 bytes
            unsigned a[2][4], bp[JP][4];
            #pragma unroll
            for (int i = 0; i < 2; i++)
                ldsm4(a[i][0], a[i][1], a[i][2], a[i][3],
                      ab + i * (16 * RS * 2) + kbb);
            #pragma unroll
            for (int jp = 0; jp < JP; jp++)
                ldsm4(bp[jp][0], bp[jp][1], bp[jp][2], bp[jp][3],
                      bb + jp * (16 * RS * 2) + kbb);
            #pragma unroll
            for (int i = 0; i < 2; i++)
                #pragma unroll
                for (int j = 0; j < JN; j++) {
                    const unsigned b0 = bp[j >> 1][(j & 1) * 2];
                    const unsigned b1 = bp[j >> 1][(j & 1) * 2 + 1];
                    asm volatile(
                        "mma.sync.aligned.m16n8k16.row.col.f32.f16.f16.f32 "
                        "{%0,%1,%2,%3}, {%4,%5,%6,%7}, {%8,%9}, {%0,%1,%2,%3};\n"
                        : "+f"(cr[i][j][0]), "+f"(cr[i][j][1]),
                          "+f"(cr[i][j][2]), "+f"(cr[i][j][3])
                        : "r"(a[i][0]), "r"(a[i][1]), "r"(a[i][2]), "r"(a[i][3]),
                          "r"(b0), "r"(b1));
                }
        }
    };

    const int nt = K / 64;
    #pragma unroll
    for (int s = 0; s < S - 1; s++) issue(s, s * 64);
    asm volatile("cp.async.wait_group %0;\n" :: "n"(S - 2));
    __syncthreads();

    for (int kt = 0; kt < nt; kt++) {
        int nk = kt + S - 1;
        if (nk < nt) issue(nk % S, nk * 64);
        else asm volatile("cp.async.commit_group;\n");
        compute(kt % S);
        asm volatile("cp.async.wait_group %0;\n" :: "n"(S - 2));
        __syncthreads();
    }

    // ---------------- epilogue ----------------
    if (!FUSED) {
        #pragma unroll
        for (int i = 0; i < 2; i++)
            #pragma unroll
            for (int j = 0; j < JN; j++) {
                int r  = row0 + wm + i * 16 + gid;
                int cn = col0 + wn + j * 8 + q * 2;
                *reinterpret_cast<float2*>(Cf + (size_t)r * ldc + cn) =
                    make_float2(cr[i][j][0], cr[i][j][1]);
                *reinterpret_cast<float2*>(Cf + (size_t)(r + 8) * ldc + cn) =
                    make_float2(cr[i][j][2], cr[i][j][3]);
            }
    } else {
        const float4* brp = reinterpret_cast<const float4*>(Brs);
        const float4* bip = reinterpret_cast<const float4*>(Bis);
        #pragma unroll
        for (int i = 0; i < 2; i++)
            #pragma unroll
            for (int j = 0; j < JN; j++) {
                int r  = row0 + wm + i * 16 + gid;
                int cn = col0 + wn + j * 8 + q * 2;
                float g0 = g_gate[cn], g1 = g_gate[cn + 1];
                *reinterpret_cast<__half2*>(Ch + (size_t)r * ldc + cn) =
                    __floats2half2_rn(cr[i][j][0] * g0, cr[i][j][1] * g1);
                *reinterpret_cast<__half2*>(Ch + (size_t)(r + 8) * ldc + cn) =
                    __floats2half2_rn(cr[i][j][2] * g0, cr[i][j][3] * g1);
                if (write_state) {
                    emit_state(nr, ni, brp, bip, r,     cn,     cr[i][j][0]);
                    emit_state(nr, ni, brp, bip, r,     cn + 1, cr[i][j][1]);
                    emit_state(nr, ni, brp, bip, r + 8, cn,     cr[i][j][2]);
                    emit_state(nr, ni, brp, bip, r + 8, cn + 1, cr[i][j][3]);
                }
            }
    }
}

// ---------------- rmsnorm + residual ----------------------------------------
__global__ __launch_bounds__(256) void rms_kernel(const float* __restrict__ x,
                                                  const float* __restrict__ w,
                                                  float* __restrict__ out)
{
    const int row = blockIdx.x;
    const float* o = g_o + (size_t)row * D_;
    float s = 0.f;
    for (int d = threadIdx.x; d < D_; d += 256) {
        float v = o[d];
        s = fmaf(v, v, s);
    }
    __shared__ float red[8];
    #pragma unroll
    for (int off = 16; off; off >>= 1) s += __shfl_xor_sync(0xFFFFFFFFu, s, off);
    if ((threadIdx.x & 31) == 0) red[threadIdx.x >> 5] = s;
    __syncthreads();
    if (threadIdx.x < 8) {
        float t = red[threadIdx.x];
        #pragma unroll
        for (int off = 4; off; off >>= 1) t += __shfl_xor_sync(0xFFu, t, off);
        if (threadIdx.x == 0) red[0] = t;
    }
    __syncthreads();
    const float scale = rsqrtf(red[0] * (1.0f / D_) + 1.1920928955078125e-7f);
    for (int d = threadIdx.x; d < D_; d += 256) {
        out[(size_t)row * D_ + d] =
            x[(size_t)row * D_ + d] + o[d] * scale * w[d];
    }
}

// ---------------- launch -----------------------------------------------------
extern "C" void kernel_launch(void* const* d_in, const int* in_sizes, int n_in,
                              void* d_out, int out_size)
{
    const float* x     = (const float*)d_in[0];
    const float* W_in  = (const float*)d_in[1];
    const float* W_out = (const float*)d_in[2];
    // d_in[3] = A_theta: dead (initial state is zero)
    const float* Br    = (const float*)d_in[4];
    const float* Bi    = (const float*)d_in[5];
    const float* Cr    = (const float*)d_in[6];
    const float* Ci    = (const float*)d_in[7];
    const float* nw    = (const float*)d_in[8];

    float* out0 = (float*)d_out;
    const long long FULL =
        (long long)BL_ * D_ + 2LL * BL_ * N1_ * DS_;   // 136,314,880
    const int write_state = ((long long)out_size >= FULL) ? 1 : 0;
    float* nr = out0 + (size_t)BL_ * D_;
    float* ni = nr + (size_t)BL_ * N1_ * DS_;

    void *w1_p = nullptr, *w2_p = nullptr, *xh_p = nullptr, *yh_p = nullptr, *o_p = nullptr;
    cudaGetSymbolAddress(&w1_p, g_Wh1);
    cudaGetSymbolAddress(&w2_p, g_Wh2);
    cudaGetSymbolAddress(&xh_p, g_xh);
    cudaGetSymbolAddress(&yh_p, g_yh);
    cudaGetSymbolAddress(&o_p,  g_o);

    const int SMEM = 4 * (64 + 128) * 72 * 2;   // 110,592 B
    cudaFuncSetAttribute(gemm_tn<true >, cudaFuncAttributeMaxDynamicSharedMemorySize, SMEM);
    cudaFuncSetAttribute(gemm_tn<false>, cudaFuncAttributeMaxDynamicSharedMemorySize, SMEM);

    // convert inputs to fp16 (single launch)
    const int na = N1_ * D_ / 4, nb = D_ * N1_ / 4, nc = BL_ * D_ / 4;
    to_half_all<<<(na + nb + nc + 255) / 256, 256>>>(
        (const float4*)W_in,  (__half2*)w1_p, na,
        (const float4*)W_out, (__half2*)w2_p, nb,
        (const float4*)x,     (__half2*)xh_p, nc);

    compute_gate<<<(4 * N1_) / 256, 256>>>((const float4*)Br, (const float4*)Bi,
                                           (const float4*)Cr, (const float4*)Ci);

    // GEMM1 (fused): xi = x @ W_in^T -> y(half) / nr / ni.  M=1024,N=4096,K=2048
    // 512 CTAs (~1.7 waves) so wave-1's nr/ni store drain overlaps wave-2 compute.
    gemm_tn<true><<<dim3(N1_ / 128, BL_ / 64), 256, SMEM>>>(
        (const __half*)xh_p, (const __half*)w1_p, nullptr, (__half*)yh_p, N1_, D_,
        Br, Bi, nr, ni, write_state);

    // GEMM2: out = y @ W_out^T.  M=1024,N=2048,K=4096
    gemm_tn<false><<<dim3(D_ / 128, BL_ / 64), 256, SMEM>>>(
        (const __half*)yh_p, (const __half*)w2_p, (float*)o_p, nullptr, D_, N1_,
        nullptr, nullptr, nullptr, nullptr, 0);

    // out0 = x + rmsnorm(out) * norm_w
    rms_kernel<<<BL_, 256>>>(x, nw, out0);
}

// round 9
// speedup vs baseline: 1.6702x; 1.5784x over previous
#include <cuda_runtime.h>
#include <cuda_fp16.h>
#include <cstdint>
#include <cstddef>

#define D_   2048
#define NC_  2
#define DS_  16
#define BL_  1024           // B*L = 2*512
#define N1_  4096           // NC*D

// ---------------- scratch (static device globals; no allocation) -----------
__device__ __half g_Wh1[(size_t)N1_ * D_];   // fp16 W_in   (16 MB)
__device__ __half g_Wh2[(size_t)D_ * N1_];   // fp16 W_out  (16 MB)
__device__ __half g_xh [(size_t)BL_ * D_];   // fp16 x      (2 MB)
__device__ __half g_xih[(size_t)BL_ * N1_];  // fp16 xi     (8 MB)
__device__ __half g_yh [(size_t)BL_ * N1_];  // fp16 y = xi*gate (8 MB)
__device__ float  g_o  [(size_t)BL_ * D_];   // out pre-norm (8 MB)
__device__ float  g_gate[N1_];

// ---------------- helpers ---------------------------------------------------
__device__ __forceinline__ void cpa16(const void* s, const void* g) {
    unsigned sa = (unsigned)__cvta_generic_to_shared(s);
    asm volatile("cp.async.cg.shared.global [%0], [%1], 16;\n" :: "r"(sa), "l"(g));
}
__device__ __forceinline__ void ldsm4(unsigned& r0, unsigned& r1,
                                      unsigned& r2, unsigned& r3, uint32_t a) {
    asm volatile("ldmatrix.sync.aligned.m8n8.x4.shared.b16 {%0,%1,%2,%3}, [%4];"
                 : "=r"(r0), "=r"(r1), "=r"(r2), "=r"(r3) : "r"(a));
}
__device__ __forceinline__ void stcs(float4* p, float4 v) {
    asm volatile("st.global.cs.v4.f32 [%0], {%1,%2,%3,%4};"
                 :: "l"(p), "f"(v.x), "f"(v.y), "f"(v.z), "f"(v.w) : "memory");
}

// ---------------- fp32 -> fp16 convert (all 3 tensors, one launch) ----------
__global__ void to_half_all(const float4* __restrict__ a, __half2* __restrict__ da, int na,
                            const float4* __restrict__ b, __half2* __restrict__ db, int nb,
                            const float4* __restrict__ c, __half2* __restrict__ dc, int nc) {
    int i = blockIdx.x * blockDim.x + threadIdx.x;
    const float4* s; __half2* d; int idx;
    if (i < na)           { s = a; d = da; idx = i; }
    else if (i < na + nb) { s = b; d = db; idx = i - na; }
    else if (i < na + nb + nc) { s = c; d = dc; idx = i - na - nb; }
    else return;
    float4 v = s[idx];
    d[2 * idx]     = __floats2half2_rn(v.x, v.y);
    d[2 * idx + 1] = __floats2half2_rn(v.z, v.w);
}

// ---------------- gate: g[n] = sum_ds(Cr*Br - Ci*Bi), 4 lanes per n ---------
__global__ void compute_gate(const float4* __restrict__ Br, const float4* __restrict__ Bi,
                             const float4* __restrict__ Cr, const float4* __restrict__ Ci) {
    int t = blockIdx.x * blockDim.x + threadIdx.x;   // 0 .. 4*N1_-1
    int n = t >> 2, j = t & 3;
    if (n >= N1_) return;
    float4 cr = Cr[n * 4 + j], br = Br[n * 4 + j];
    float4 ci = Ci[n * 4 + j], bi = Bi[n * 4 + j];
    float s = 0.f;
    s = fmaf(cr.x, br.x, s); s = fmaf(-ci.x, bi.x, s);
    s = fmaf(cr.y, br.y, s); s = fmaf(-ci.y, bi.y, s);
    s = fmaf(cr.z, br.z, s); s = fmaf(-ci.z, bi.z, s);
    s = fmaf(cr.w, br.w, s); s = fmaf(-ci.w, bi.w, s);
    s += __shfl_down_sync(0xFFFFFFFFu, s, 2);
    s += __shfl_down_sync(0xFFFFFFFFu, s, 1);
    if (j == 0) g_gate[n] = s;
}

// ---------------- y = xi * gate (fp16, coalesced 16B) ------------------------
__global__ void ew_y(const int4* __restrict__ xi, int4* __restrict__ y) {
    int i = blockIdx.x * blockDim.x + threadIdx.x;   // 8 halves per thread
    if (i >= BL_ * N1_ / 8) return;
    int col0 = (i * 8) & (N1_ - 1);
    int4 v = xi[i];
    const __half2* h = reinterpret_cast<const __half2*>(&v);
    float4 ga = *reinterpret_cast<const float4*>(&g_gate[col0]);
    float4 gb = *reinterpret_cast<const float4*>(&g_gate[col0 + 4]);
    int4 o;
    __half2* ho = reinterpret_cast<__half2*>(&o);
    float2 f;
    f = __half22float2(h[0]); ho[0] = __floats2half2_rn(f.x * ga.x, f.y * ga.y);
    f = __half22float2(h[1]); ho[1] = __floats2half2_rn(f.x * ga.z, f.y * ga.w);
    f = __half22float2(h[2]); ho[2] = __floats2half2_rn(f.x * gb.x, f.y * gb.y);
    f = __half22float2(h[3]); ho[3] = __floats2half2_rn(f.x * gb.z, f.y * gb.w);
    y[i] = o;
}

// ---------------- state emission: nr = Br*xi, ni = Bi*xi (coalesced) --------
// thread t handles float4 index t of nr AND ni:
//   t = row*16384 + col*4 + jj  (row<1024, col<4096, jj<4)
__global__ void ew_state(const __half* __restrict__ xi,
                         const float4* __restrict__ brp, const float4* __restrict__ bip,
                         float4* __restrict__ nr4, float4* __restrict__ ni4) {
    int t = blockIdx.x * blockDim.x + threadIdx.x;
    if (t >= BL_ * N1_ * 4) return;
    int row = t >> 14;
    int idx = t & 16383;
    int col = idx >> 2;
    int jj  = idx & 3;
    float v = __half2float(__ldg(&xi[(size_t)row * N1_ + col]));
    float4 br = __ldg(&brp[col * 4 + jj]);
    stcs(&nr4[t], make_float4(br.x * v, br.y * v, br.z * v, br.w * v));
    float4 bi = __ldg(&bip[col * 4 + jj]);
    stcs(&ni4[t], make_float4(bi.x * v, bi.y * v, bi.z * v, bi.w * v));
}

// ---------------- TN GEMM: C[M,N] = A[M,K] * B[N,K]^T (fp16 mma + ldmatrix) -
// 64 x 128 CTA tile, BK=64 halves, 4-stage cp.async pipeline, 256 threads.
// HALF_OUT: write fp16 accumulators (xi); else fp32 (o).
template<bool HALF_OUT>
__global__ __launch_bounds__(256, 2) void gemm_tn(
    const __half* __restrict__ A, const __half* __restrict__ B,
    float* __restrict__ Cf, __half* __restrict__ Ch, int ldc, int K)
{
    constexpr int S   = 4;                    // pipeline stages
    constexpr int BM  = 64;
    constexpr int RS  = 72;                   // halves per smem row (64 + 8 pad)
    constexpr int WR  = 2;                    // warps along m
    constexpr int WNS = 32;                   // warp n-extent
    constexpr int JN  = WNS / 8;              // 4
    constexpr int JP  = JN / 2;               // 2 ldmatrix B pairs
    constexpr int AST = BM  * RS;             // halves per A stage
    constexpr int BST = 128 * RS;

    extern __shared__ __half sm[];

    const int tid  = threadIdx.x;
    const int lane = tid & 31;
    const int wid  = tid >> 5;
    const int wm   = (wid % WR) * 32;
    const int wn   = (wid / WR) * WNS;
    const int gid  = lane >> 2;
    const int q    = lane & 3;
    const int row0 = blockIdx.y * BM;
    const int col0 = blockIdx.x * 128;

    const int lr = tid >> 3;                  // loader row (0..31)
    const int ls = (tid & 7) * 8;             // loader half-offset (16B = 8 halves)

    // ldmatrix per-lane address offsets (bytes)
    const int lr8 = lane & 7;
    const int lg  = lane >> 3;                // 0..3
    const uint32_t sm_u = (uint32_t)__cvta_generic_to_shared(sm);
    const uint32_t A_u  = sm_u;
    const uint32_t B_u  = sm_u + S * AST * 2;
    const uint32_t a_off = (uint32_t)(((wm + (lg & 1) * 8 + lr8) * RS + (lg >> 1) * 8) * 2);
    const uint32_t b_off = (uint32_t)(((wn + (lg >> 1) * 8 + lr8) * RS + (lg & 1) * 8) * 2);

    __half* As = sm;
    __half* Bs = sm + S * AST;

    float cr[2][JN][4];
    #pragma unroll
    for (int i = 0; i < 2; i++)
        #pragma unroll
        for (int j = 0; j < JN; j++)
            #pragma unroll
            for (int t = 0; t < 4; t++) cr[i][j][t] = 0.f;

    auto issue = [&](int st, int k0) {
        #pragma unroll
        for (int i = 0; i < BM / 32; i++) {            // 2 A-row groups
            int r = lr + i * 32;
            cpa16(&As[st * AST + r * RS + ls], A + (size_t)(row0 + r) * K + k0 + ls);
        }
        #pragma unroll
        for (int i = 0; i < 4; i++) {                  // 4 B-row groups
            int r = lr + i * 32;
            cpa16(&Bs[st * BST + r * RS + ls], B + (size_t)(col0 + r) * K + k0 + ls);
        }
        asm volatile("cp.async.commit_group;\n");
    };

    auto compute = [&](int st) {
        const uint32_t ab = A_u + st * (AST * 2) + a_off;
        const uint32_t bb = B_u + st * (BST * 2) + b_off;
        #pragma unroll
        for (int ks = 0; ks < 4; ks++) {               // 4 k-halves of 16
            const uint32_t kbb = ks * 32;              // 16 halves = 32 bytes
            unsigned a[2][4], bp[JP][4];
            #pragma unroll
            for (int i = 0; i < 2; i++)
                ldsm4(a[i][0], a[i][1], a[i][2], a[i][3],
                      ab + i * (16 * RS * 2) + kbb);
            #pragma unroll
            for (int jp = 0; jp < JP; jp++)
                ldsm4(bp[jp][0], bp[jp][1], bp[jp][2], bp[jp][3],
                      bb + jp * (16 * RS * 2) + kbb);
            #pragma unroll
            for (int i = 0; i < 2; i++)
                #pragma unroll
                for (int j = 0; j < JN; j++) {
                    const unsigned b0 = bp[j >> 1][(j & 1) * 2];
                    const unsigned b1 = bp[j >> 1][(j & 1) * 2 + 1];
                    asm volatile(
                        "mma.sync.aligned.m16n8k16.row.col.f32.f16.f16.f32 "
                        "{%0,%1,%2,%3}, {%4,%5,%6,%7}, {%8,%9}, {%0,%1,%2,%3};\n"
                        : "+f"(cr[i][j][0]), "+f"(cr[i][j][1]),
                          "+f"(cr[i][j][2]), "+f"(cr[i][j][3])
                        : "r"(a[i][0]), "r"(a[i][1]), "r"(a[i][2]), "r"(a[i][3]),
                          "r"(b0), "r"(b1));
                }
        }
    };

    const int nt = K / 64;
    #pragma unroll
    for (int s = 0; s < S - 1; s++) issue(s, s * 64);
    asm volatile("cp.async.wait_group %0;\n" :: "n"(S - 2));
    __syncthreads();

    for (int kt = 0; kt < nt; kt++) {
        int nk = kt + S - 1;
        if (nk < nt) issue(nk % S, nk * 64);
        else asm volatile("cp.async.commit_group;\n");
        compute(kt % S);
        asm volatile("cp.async.wait_group %0;\n" :: "n"(S - 2));
        __syncthreads();
    }

    // ---------------- epilogue (plain accumulator store) ----------
    #pragma unroll
    for (int i = 0; i < 2; i++)
        #pragma unroll
        for (int j = 0; j < JN; j++) {
            int r  = row0 + wm + i * 16 + gid;
            int cn = col0 + wn + j * 8 + q * 2;
            if (HALF_OUT) {
                *reinterpret_cast<__half2*>(Ch + (size_t)r * ldc + cn) =
                    __floats2half2_rn(cr[i][j][0], cr[i][j][1]);
                *reinterpret_cast<__half2*>(Ch + (size_t)(r + 8) * ldc + cn) =
                    __floats2half2_rn(cr[i][j][2], cr[i][j][3]);
            } else {
                *reinterpret_cast<float2*>(Cf + (size_t)r * ldc + cn) =
                    make_float2(cr[i][j][0], cr[i][j][1]);
                *reinterpret_cast<float2*>(Cf + (size_t)(r + 8) * ldc + cn) =
                    make_float2(cr[i][j][2], cr[i][j][3]);
            }
        }
}

// ---------------- rmsnorm + residual ----------------------------------------
__global__ __launch_bounds__(256) void rms_kernel(const float* __restrict__ x,
                                                  const float* __restrict__ w,
                                                  float* __restrict__ out)
{
    const int row = blockIdx.x;
    const float* o = g_o + (size_t)row * D_;
    float s = 0.f;
    for (int d = threadIdx.x; d < D_; d += 256) {
        float v = o[d];
        s = fmaf(v, v, s);
    }
    __shared__ float red[8];
    #pragma unroll
    for (int off = 16; off; off >>= 1) s += __shfl_xor_sync(0xFFFFFFFFu, s, off);
    if ((threadIdx.x & 31) == 0) red[threadIdx.x >> 5] = s;
    __syncthreads();
    if (threadIdx.x < 8) {
        float t = red[threadIdx.x];
        #pragma unroll
        for (int off = 4; off; off >>= 1) t += __shfl_xor_sync(0xFFu, t, off);
        if (threadIdx.x == 0) red[0] = t;
    }
    __syncthreads();
    const float scale = rsqrtf(red[0] * (1.0f / D_) + 1.1920928955078125e-7f);
    for (int d = threadIdx.x; d < D_; d += 256) {
        out[(size_t)row * D_ + d] =
            x[(size_t)row * D_ + d] + o[d] * scale * w[d];
    }
}

// ---------------- launch -----------------------------------------------------
extern "C" void kernel_launch(void* const* d_in, const int* in_sizes, int n_in,
                              void* d_out, int out_size)
{
    const float* x     = (const float*)d_in[0];
    const float* W_in  = (const float*)d_in[1];
    const float* W_out = (const float*)d_in[2];
    // d_in[3] = A_theta: dead (initial state is zero)
    const float* Br    = (const float*)d_in[4];
    const float* Bi    = (const float*)d_in[5];
    const float* Cr    = (const float*)d_in[6];
    const float* Ci    = (const float*)d_in[7];
    const float* nw    = (const float*)d_in[8];

    float* out0 = (float*)d_out;
    const long long FULL =
        (long long)BL_ * D_ + 2LL * BL_ * N1_ * DS_;   // 136,314,880
    const int write_state = ((long long)out_size >= FULL) ? 1 : 0;
    float* nr = out0 + (size_t)BL_ * D_;
    float* ni = nr + (size_t)BL_ * N1_ * DS_;

    void *w1_p = nullptr, *w2_p = nullptr, *xh_p = nullptr, *xih_p = nullptr,
         *yh_p = nullptr, *o_p = nullptr;
    cudaGetSymbolAddress(&w1_p,  g_Wh1);
    cudaGetSymbolAddress(&w2_p,  g_Wh2);
    cudaGetSymbolAddress(&xh_p,  g_xh);
    cudaGetSymbolAddress(&xih_p, g_xih);
    cudaGetSymbolAddress(&yh_p,  g_yh);
    cudaGetSymbolAddress(&o_p,   g_o);

    const int SMEM = 4 * (64 + 128) * 72 * 2;   // 110,592 B
    cudaFuncSetAttribute(gemm_tn<true >, cudaFuncAttributeMaxDynamicSharedMemorySize, SMEM);
    cudaFuncSetAttribute(gemm_tn<false>, cudaFuncAttributeMaxDynamicSharedMemorySize, SMEM);

    // convert inputs to fp16 (single launch)
    const int na = N1_ * D_ / 4, nb = D_ * N1_ / 4, nc = BL_ * D_ / 4;
    to_half_all<<<(na + nb + nc + 255) / 256, 256>>>(
        (const float4*)W_in,  (__half2*)w1_p, na,
        (const float4*)W_out, (__half2*)w2_p, nb,
        (const float4*)x,     (__half2*)xh_p, nc);

    compute_gate<<<(4 * N1_) / 256, 256>>>((const float4*)Br, (const float4*)Bi,
                                           (const float4*)Cr, (const float4*)Ci);

    // GEMM1: xi = x @ W_in^T (fp16 out).  M=1024,N=4096,K=2048
    gemm_tn<true><<<dim3(N1_ / 128, BL_ / 64), 256, SMEM>>>(
        (const __half*)xh_p, (const __half*)w1_p, nullptr, (__half*)xih_p, N1_, D_);

    // y = xi * gate
    ew_y<<<(BL_ * N1_ / 8 + 255) / 256, 256>>>((const int4*)xih_p, (int4*)yh_p);

    // GEMM2: out = y @ W_out^T.  M=1024,N=2048,K=4096
    gemm_tn<false><<<dim3(D_ / 128, BL_ / 64), 256, SMEM>>>(
        (const __half*)yh_p, (const __half*)w2_p, (float*)o_p, nullptr, D_, N1_);

    // nr/ni emission (coalesced streaming)
    if (write_state) {
        ew_state<<<(BL_ * N1_ * 4) / 256, 256>>>(
            (const __half*)xih_p,
            (const float4*)Br, (const float4*)Bi,
            (float4*)nr, (float4*)ni);
    }

    // out0 = x + rmsnorm(out) * norm_w
    rms_kernel<<<BL_, 256>>>(x, nw, out0);
}

// round 10
// speedup vs baseline: 1.7245x; 1.0325x over previous
#include <cuda_runtime.h>
#include <cuda_fp16.h>
#include <cstdint>
#include <cstddef>

#define D_   2048
#define NC_  2
#define DS_  16
#define BL_  1024           // B*L = 2*512
#define N1_  4096           // NC*D

// ---------------- scratch (static device globals; no allocation) -----------
__device__ __half g_Wh1[(size_t)N1_ * D_];   // fp16 W_in   (16 MB)
__device__ __half g_Wh2[(size_t)D_ * N1_];   // fp16 W_out  (16 MB)
__device__ __half g_xh [(size_t)BL_ * D_];   // fp16 x      (2 MB)
__device__ __half g_xih[(size_t)BL_ * N1_];  // fp16 xi     (8 MB)
__device__ __half g_yh [(size_t)BL_ * N1_];  // fp16 y = xi*gate (8 MB)
__device__ float  g_o  [(size_t)BL_ * D_];   // out pre-norm (8 MB)
__device__ float  g_gate[N1_];

// ---------------- helpers ---------------------------------------------------
__device__ __forceinline__ void cpa16(const void* s, const void* g) {
    unsigned sa = (unsigned)__cvta_generic_to_shared(s);
    asm volatile("cp.async.cg.shared.global [%0], [%1], 16;\n" :: "r"(sa), "l"(g));
}
__device__ __forceinline__ void ldsm4(unsigned& r0, unsigned& r1,
                                      unsigned& r2, unsigned& r3, uint32_t a) {
    asm volatile("ldmatrix.sync.aligned.m8n8.x4.shared.b16 {%0,%1,%2,%3}, [%4];"
                 : "=r"(r0), "=r"(r1), "=r"(r2), "=r"(r3) : "r"(a));
}
__device__ __forceinline__ void stcs(float4* p, float4 v) {
    asm volatile("st.global.cs.v4.f32 [%0], {%1,%2,%3,%4};"
                 :: "l"(p), "f"(v.x), "f"(v.y), "f"(v.z), "f"(v.w) : "memory");
}

// ---------------- fp32 -> fp16 convert --------------------------------------
__global__ void to_half(const float4* __restrict__ s, __half2* __restrict__ d, int n4) {
    int i = blockIdx.x * blockDim.x + threadIdx.x;
    if (i >= n4) return;
    float4 v = s[i];
    d[2 * i]     = __floats2half2_rn(v.x, v.y);
    d[2 * i + 1] = __floats2half2_rn(v.z, v.w);
}
__global__ void to_half2(const float4* __restrict__ a, __half2* __restrict__ da, int na,
                         const float4* __restrict__ b, __half2* __restrict__ db, int nb) {
    int i = blockIdx.x * blockDim.x + threadIdx.x;
    const float4* s; __half2* d; int idx;
    if (i < na)           { s = a; d = da; idx = i; }
    else if (i < na + nb) { s = b; d = db; idx = i - na; }
    else return;
    float4 v = s[idx];
    d[2 * idx]     = __floats2half2_rn(v.x, v.y);
    d[2 * idx + 1] = __floats2half2_rn(v.z, v.w);
}

// ---------------- gate: g[n] = sum_ds(Cr*Br - Ci*Bi), 4 lanes per n ---------
__global__ void compute_gate(const float4* __restrict__ Br, const float4* __restrict__ Bi,
                             const float4* __restrict__ Cr, const float4* __restrict__ Ci) {
    int t = blockIdx.x * blockDim.x + threadIdx.x;   // 0 .. 4*N1_-1
    int n = t >> 2, j = t & 3;
    if (n >= N1_) return;
    float4 cr = Cr[n * 4 + j], br = Br[n * 4 + j];
    float4 ci = Ci[n * 4 + j], bi = Bi[n * 4 + j];
    float s = 0.f;
    s = fmaf(cr.x, br.x, s); s = fmaf(-ci.x, bi.x, s);
    s = fmaf(cr.y, br.y, s); s = fmaf(-ci.y, bi.y, s);
    s = fmaf(cr.z, br.z, s); s = fmaf(-ci.z, bi.z, s);
    s = fmaf(cr.w, br.w, s); s = fmaf(-ci.w, bi.w, s);
    s += __shfl_down_sync(0xFFFFFFFFu, s, 2);
    s += __shfl_down_sync(0xFFFFFFFFu, s, 1);
    if (j == 0) g_gate[n] = s;
}

// ---------------- y = xi * gate (fp16, coalesced 16B) ------------------------
__global__ void ew_y(const int4* __restrict__ xi, int4* __restrict__ y) {
    int i = blockIdx.x * blockDim.x + threadIdx.x;   // 8 halves per thread
    if (i >= BL_ * N1_ / 8) return;
    int col0 = (i * 8) & (N1_ - 1);
    int4 v = xi[i];
    const __half2* h = reinterpret_cast<const __half2*>(&v);
    float4 ga = *reinterpret_cast<const float4*>(&g_gate[col0]);
    float4 gb = *reinterpret_cast<const float4*>(&g_gate[col0 + 4]);
    int4 o;
    __half2* ho = reinterpret_cast<__half2*>(&o);
    float2 f;
    f = __half22float2(h[0]); ho[0] = __floats2half2_rn(f.x * ga.x, f.y * ga.y);
    f = __half22float2(h[1]); ho[1] = __floats2half2_rn(f.x * ga.z, f.y * ga.w);
    f = __half22float2(h[2]); ho[2] = __floats2half2_rn(f.x * gb.x, f.y * gb.y);
    f = __half22float2(h[3]); ho[3] = __floats2half2_rn(f.x * gb.z, f.y * gb.w);
    y[i] = o;
}

// ---------------- state emission: nr = Br*xi, ni = Bi*xi (coalesced) --------
__global__ void ew_state(const __half* __restrict__ xi,
                         const float4* __restrict__ brp, const float4* __restrict__ bip,
                         float4* __restrict__ nr4, float4* __restrict__ ni4) {
    int t = blockIdx.x * blockDim.x + threadIdx.x;
    if (t >= BL_ * N1_ * 4) return;
    int row = t >> 14;
    int idx = t & 16383;
    int col = idx >> 2;
    int jj  = idx & 3;
    float v = __half2float(__ldg(&xi[(size_t)row * N1_ + col]));
    float4 br = __ldg(&brp[col * 4 + jj]);
    stcs(&nr4[t], make_float4(br.x * v, br.y * v, br.z * v, br.w * v));
    float4 bi = __ldg(&bip[col * 4 + jj]);
    stcs(&ni4[t], make_float4(bi.x * v, bi.y * v, bi.z * v, bi.w * v));
}

// ---------------- TN GEMM: C[M,N] = A[M,K] * B[N,K]^T (fp16 mma + ldmatrix) -
// 64 x 128 CTA tile, BK=64 halves, 4-stage cp.async pipeline, 256 threads.
template<bool HALF_OUT>
__global__ __launch_bounds__(256, 2) void gemm_tn(
    const __half* __restrict__ A, const __half* __restrict__ B,
    float* __restrict__ Cf, __half* __restrict__ Ch, int ldc, int K)
{
    constexpr int S   = 4;
    constexpr int BM  = 64;
    constexpr int RS  = 72;                   // halves per smem row (64 + 8 pad)
    constexpr int WR  = 2;
    constexpr int WNS = 32;
    constexpr int JN  = WNS / 8;              // 4
    constexpr int JP  = JN / 2;               // 2 ldmatrix B pairs
    constexpr int AST = BM  * RS;
    constexpr int BST = 128 * RS;

    extern __shared__ __half sm[];

    const int tid  = threadIdx.x;
    const int lane = tid & 31;
    const int wid  = tid >> 5;
    const int wm   = (wid % WR) * 32;
    const int wn   = (wid / WR) * WNS;
    const int gid  = lane >> 2;
    const int q    = lane & 3;
    const int row0 = blockIdx.y * BM;
    const int col0 = blockIdx.x * 128;

    const int lr = tid >> 3;                  // loader row (0..31)
    const int ls = (tid & 7) * 8;             // loader half-offset

    const int lr8 = lane & 7;
    const int lg  = lane >> 3;                // 0..3
    const uint32_t sm_u = (uint32_t)__cvta_generic_to_shared(sm);
    const uint32_t A_u  = sm_u;
    const uint32_t B_u  = sm_u + S * AST * 2;
    const uint32_t a_off = (uint32_t)(((wm + (lg & 1) * 8 + lr8) * RS + (lg >> 1) * 8) * 2);
    const uint32_t b_off = (uint32_t)(((wn + (lg >> 1) * 8 + lr8) * RS + (lg & 1) * 8) * 2);

    __half* As = sm;
    __half* Bs = sm + S * AST;

    float cr[2][JN][4];
    #pragma unroll
    for (int i = 0; i < 2; i++)
        #pragma unroll
        for (int j = 0; j < JN; j++)
            #pragma unroll
            for (int t = 0; t < 4; t++) cr[i][j][t] = 0.f;

    auto issue = [&](int st, int k0) {
        #pragma unroll
        for (int i = 0; i < BM / 32; i++) {
            int r = lr + i * 32;
            cpa16(&As[st * AST + r * RS + ls], A + (size_t)(row0 + r) * K + k0 + ls);
        }
        #pragma unroll
        for (int i = 0; i < 4; i++) {
            int r = lr + i * 32;
            cpa16(&Bs[st * BST + r * RS + ls], B + (size_t)(col0 + r) * K + k0 + ls);
        }
        asm volatile("cp.async.commit_group;\n");
    };

    auto compute = [&](int st) {
        const uint32_t ab = A_u + st * (AST * 2) + a_off;
        const uint32_t bb = B_u + st * (BST * 2) + b_off;
        #pragma unroll
        for (int ks = 0; ks < 4; ks++) {
            const uint32_t kbb = ks * 32;
            unsigned a[2][4], bp[JP][4];
            #pragma unroll
            for (int i = 0; i < 2; i++)
                ldsm4(a[i][0], a[i][1], a[i][2], a[i][3],
                      ab + i * (16 * RS * 2) + kbb);
            #pragma unroll
            for (int jp = 0; jp < JP; jp++)
                ldsm4(bp[jp][0], bp[jp][1], bp[jp][2], bp[jp][3],
                      bb + jp * (16 * RS * 2) + kbb);
            #pragma unroll
            for (int i = 0; i < 2; i++)
                #pragma unroll
                for (int j = 0; j < JN; j++) {
                    const unsigned b0 = bp[j >> 1][(j & 1) * 2];
                    const unsigned b1 = bp[j >> 1][(j & 1) * 2 + 1];
                    asm volatile(
                        "mma.sync.aligned.m16n8k16.row.col.f32.f16.f16.f32 "
                        "{%0,%1,%2,%3}, {%4,%5,%6,%7}, {%8,%9}, {%0,%1,%2,%3};\n"
                        : "+f"(cr[i][j][0]), "+f"(cr[i][j][1]),
                          "+f"(cr[i][j][2]), "+f"(cr[i][j][3])
                        : "r"(a[i][0]), "r"(a[i][1]), "r"(a[i][2]), "r"(a[i][3]),
                          "r"(b0), "r"(b1));
                }
        }
    };

    const int nt = K / 64;
    #pragma unroll
    for (int s = 0; s < S - 1; s++) issue(s, s * 64);
    asm volatile("cp.async.wait_group %0;\n" :: "n"(S - 2));
    __syncthreads();

    for (int kt = 0; kt < nt; kt++) {
        int nk = kt + S - 1;
        if (nk < nt) issue(nk % S, nk * 64);
        else asm volatile("cp.async.commit_group;\n");
        compute(kt % S);
        asm volatile("cp.async.wait_group %0;\n" :: "n"(S - 2));
        __syncthreads();
    }

    #pragma unroll
    for (int i = 0; i < 2; i++)
        #pragma unroll
        for (int j = 0; j < JN; j++) {
            int r  = row0 + wm + i * 16 + gid;
            int cn = col0 + wn + j * 8 + q * 2;
            if (HALF_OUT) {
                *reinterpret_cast<__half2*>(Ch + (size_t)r * ldc + cn) =
                    __floats2half2_rn(cr[i][j][0], cr[i][j][1]);
                *reinterpret_cast<__half2*>(Ch + (size_t)(r + 8) * ldc + cn) =
                    __floats2half2_rn(cr[i][j][2], cr[i][j][3]);
            } else {
                *reinterpret_cast<float2*>(Cf + (size_t)r * ldc + cn) =
                    make_float2(cr[i][j][0], cr[i][j][1]);
                *reinterpret_cast<float2*>(Cf + (size_t)(r + 8) * ldc + cn) =
                    make_float2(cr[i][j][2], cr[i][j][3]);
            }
        }
}

// ---------------- rmsnorm + residual ----------------------------------------
__global__ __launch_bounds__(256) void rms_kernel(const float* __restrict__ x,
                                                  const float* __restrict__ w,
                                                  float* __restrict__ out)
{
    const int row = blockIdx.x;
    const float* o = g_o + (size_t)row * D_;
    float s = 0.f;
    for (int d = threadIdx.x; d < D_; d += 256) {
        float v = o[d];
        s = fmaf(v, v, s);
    }
    __shared__ float red[8];
    #pragma unroll
    for (int off = 16; off; off >>= 1) s += __shfl_xor_sync(0xFFFFFFFFu, s, off);
    if ((threadIdx.x & 31) == 0) red[threadIdx.x >> 5] = s;
    __syncthreads();
    if (threadIdx.x < 8) {
        float t = red[threadIdx.x];
        #pragma unroll
        for (int off = 4; off; off >>= 1) t += __shfl_xor_sync(0xFFu, t, off);
        if (threadIdx.x == 0) red[0] = t;
    }
    __syncthreads();
    const float scale = rsqrtf(red[0] * (1.0f / D_) + 1.1920928955078125e-7f);
    for (int d = threadIdx.x; d < D_; d += 256) {
        out[(size_t)row * D_ + d] =
            x[(size_t)row * D_ + d] + o[d] * scale * w[d];
    }
}

// ---------------- launch -----------------------------------------------------
extern "C" void kernel_launch(void* const* d_in, const int* in_sizes, int n_in,
                              void* d_out, int out_size)
{
    const float* x     = (const float*)d_in[0];
    const float* W_in  = (const float*)d_in[1];
    const float* W_out = (const float*)d_in[2];
    // d_in[3] = A_theta: dead (initial state is zero)
    const float* Br    = (const float*)d_in[4];
    const float* Bi    = (const float*)d_in[5];
    const float* Cr    = (const float*)d_in[6];
    const float* Ci    = (const float*)d_in[7];
    const float* nw    = (const float*)d_in[8];

    float* out0 = (float*)d_out;
    const long long FULL =
        (long long)BL_ * D_ + 2LL * BL_ * N1_ * DS_;   // 136,314,880
    const int write_state = ((long long)out_size >= FULL) ? 1 : 0;
    float* nr = out0 + (size_t)BL_ * D_;
    float* ni = nr + (size_t)BL_ * N1_ * DS_;

    void *w1_p = nullptr, *w2_p = nullptr, *xh_p = nullptr, *xih_p = nullptr,
         *yh_p = nullptr, *o_p = nullptr;
    cudaGetSymbolAddress(&w1_p,  g_Wh1);
    cudaGetSymbolAddress(&w2_p,  g_Wh2);
    cudaGetSymbolAddress(&xh_p,  g_xh);
    cudaGetSymbolAddress(&xih_p, g_xih);
    cudaGetSymbolAddress(&yh_p,  g_yh);
    cudaGetSymbolAddress(&o_p,   g_o);

    const int SMEM = 4 * (64 + 128) * 72 * 2;   // 110,592 B
    cudaFuncSetAttribute(gemm_tn<true >, cudaFuncAttributeMaxDynamicSharedMemorySize, SMEM);
    cudaFuncSetAttribute(gemm_tn<false>, cudaFuncAttributeMaxDynamicSharedMemorySize, SMEM);

    // Lazily create side stream + events ONCE (correctness call runs before
    // graph capture, so no stream/event creation happens inside capture).
    static cudaStream_t side = nullptr;
    static cudaEvent_t evF = nullptr, evW2 = nullptr, evXI = nullptr, evST = nullptr;
    if (!side) {
        if (cudaStreamCreateWithFlags(&side, cudaStreamNonBlocking) != cudaSuccess)
            side = nullptr;
        if (side) {
            cudaEventCreateWithFlags(&evF,  cudaEventDisableTiming);
            cudaEventCreateWithFlags(&evW2, cudaEventDisableTiming);
            cudaEventCreateWithFlags(&evXI, cudaEventDisableTiming);
            cudaEventCreateWithFlags(&evST, cudaEventDisableTiming);
        }
    }
    const bool fork = (side != nullptr);

    const int na = N1_ * D_ / 4;   // W_in float4 count
    const int nb = D_ * N1_ / 4;   // W_out float4 count
    const int nc = BL_ * D_ / 4;   // x float4 count

    if (fork) {
        // fork side stream off the capture/main stream
        cudaEventRecord(evF, 0);
        cudaStreamWaitEvent(side, evF, 0);

        // side: convert W_out (only needed by GEMM2)
        to_half<<<(nb + 255) / 256, 256, 0, side>>>(
            (const float4*)W_out, (__half2*)w2_p, nb);
        cudaEventRecord(evW2, side);

        // main: convert W_in + x, gate, GEMM1
        to_half2<<<(na + nc + 255) / 256, 256>>>(
            (const float4*)W_in, (__half2*)w1_p, na,
            (const float4*)x,    (__half2*)xh_p, nc);
        compute_gate<<<(4 * N1_) / 256, 256>>>(
            (const float4*)Br, (const float4*)Bi,
            (const float4*)Cr, (const float4*)Ci);
        gemm_tn<true><<<dim3(N1_ / 128, BL_ / 64), 256, SMEM>>>(
            (const __half*)xh_p, (const __half*)w1_p, nullptr, (__half*)xih_p, N1_, D_);

        // side: nr/ni emission runs concurrently with ew_y + GEMM2 + rms
        cudaEventRecord(evXI, 0);
        cudaStreamWaitEvent(side, evXI, 0);
        if (write_state) {
            ew_state<<<(BL_ * N1_ * 4) / 256, 256, 0, side>>>(
                (const __half*)xih_p,
                (const float4*)Br, (const float4*)Bi,
                (float4*)nr, (float4*)ni);
        }
        cudaEventRecord(evST, side);

        // main: y, GEMM2 (needs W_out converted), rms
        ew_y<<<(BL_ * N1_ / 8 + 255) / 256, 256>>>((const int4*)xih_p, (int4*)yh_p);
        cudaStreamWaitEvent(0, evW2, 0);
        gemm_tn<false><<<dim3(D_ / 128, BL_ / 64), 256, SMEM>>>(
            (const __half*)yh_p, (const __half*)w2_p, (float*)o_p, nullptr, D_, N1_);
        rms_kernel<<<BL_, 256>>>(x, nw, out0);

        // join side back into main before capture ends
        cudaStreamWaitEvent(0, evST, 0);
    } else {
        // serial fallback (identical work)
        to_half<<<(nb + 255) / 256, 256>>>((const float4*)W_out, (__half2*)w2_p, nb);
        to_half2<<<(na + nc + 255) / 256, 256>>>(
            (const float4*)W_in, (__half2*)w1_p, na,
            (const float4*)x,    (__half2*)xh_p, nc);
        compute_gate<<<(4 * N1_) / 256, 256>>>(
            (const float4*)Br, (const float4*)Bi,
            (const float4*)Cr, (const float4*)Ci);
        gemm_tn<true><<<dim3(N1_ / 128, BL_ / 64), 256, SMEM>>>(
            (const __half*)xh_p, (const __half*)w1_p, nullptr, (__half*)xih_p, N1_, D_);
        ew_y<<<(BL_ * N1_ / 8 + 255) / 256, 256>>>((const int4*)xih_p, (int4*)yh_p);
        gemm_tn<false><<<dim3(D_ / 128, BL_ / 64), 256, SMEM>>>(
            (const __half*)yh_p, (const __half*)w2_p, (float*)o_p, nullptr, D_, N1_);
        if (write_state) {
            ew_state<<<(BL_ * N1_ * 4) / 256, 256>>>(
                (const __half*)xih_p,
                (const float4*)Br, (const float4*)Bi,
                (float4*)nr, (float4*)ni);
        }
        rms_kernel<<<BL_, 256>>>(x, nw, out0);
    }
}